// round 8
// baseline (speedup 1.0000x reference)
#include <cuda_runtime.h>
#include <cstdint>
#include <cstddef>

typedef unsigned long long ull;
#define BATCH 131072

// ---------------- f32x2 packed FMA helpers (PTX-only FFMA2) ----------------
__device__ __forceinline__ ull dup2(float v) {
    ull r;
    asm("mov.b64 %0, {%1, %1};" : "=l"(r) : "r"(__float_as_uint(v)));
    return r;
}
__device__ __forceinline__ void unpack2(ull v, float& lo, float& hi) {
    unsigned a, b;
    asm("mov.b64 {%0, %1}, %2;" : "=r"(a), "=r"(b) : "l"(v));
    lo = __uint_as_float(a); hi = __uint_as_float(b);
}
__device__ __forceinline__ void fma2(ull& d, ull a, ull b) {
    asm("fma.rn.f32x2 %0, %1, %2, %0;" : "+l"(d) : "l"(a), "l"(b));
}
__device__ __forceinline__ float gelu(float x) {
    return 0.5f * x * (1.0f + erff(x * 0.70710678118654752440f));
}

// ---------------- scratch (device globals; no cudaMalloc) ----------------
__device__ float g_h1[(size_t)BATCH * 512];
__device__ float g_mid[(size_t)BATCH * 256];
__device__ float g_pw[(size_t)BATCH * 16];
__device__ float g_part[(size_t)4 * BATCH * 128];
__device__ float g_mo[(size_t)BATCH * 128];

// ---------------- generic GEMM: C[M,N] = act(A@W^T + b) ----------------
// BM=128 BN=64 BK=16, 256 threads, per-thread 8(M)x4(N) via f32x2.
__global__ void __launch_bounds__(256, 2) k_dense(
    const float* __restrict__ A, const float* __restrict__ W,
    const float* __restrict__ bias, float* __restrict__ C,
    int K, int N, int lda, int ldw, int act)
{
    __shared__ float As[16][128];
    __shared__ ull Wd[16][64];
    const int tid = threadIdx.x;
    const int m0 = blockIdx.y << 7, n0 = blockIdx.x << 6;
    const int tx = tid & 15, ty = tid >> 4;
    const int arow = tid >> 1, ah = (tid & 1) << 3;
    const int wn = tid >> 2, wq = (tid & 3) << 2;
    const float* Ap = A + (size_t)(m0 + arow) * lda + ah;
    const float* Wp = W + (size_t)(n0 + wn) * ldw + wq;

    ull acc[4][4];
#pragma unroll
    for (int p = 0; p < 4; p++)
#pragma unroll
        for (int j = 0; j < 4; j++) acc[p][j] = 0ULL;

    for (int k0 = 0; k0 < K; k0 += 16) {
        float4 a0 = *(const float4*)(Ap + k0);
        float4 a1 = *(const float4*)(Ap + k0 + 4);
        float4 wv = *(const float4*)(Wp + k0);
        __syncthreads();
        As[ah + 0][arow] = a0.x; As[ah + 1][arow] = a0.y;
        As[ah + 2][arow] = a0.z; As[ah + 3][arow] = a0.w;
        As[ah + 4][arow] = a1.x; As[ah + 5][arow] = a1.y;
        As[ah + 6][arow] = a1.z; As[ah + 7][arow] = a1.w;
        Wd[wq + 0][wn] = dup2(wv.x); Wd[wq + 1][wn] = dup2(wv.y);
        Wd[wq + 2][wn] = dup2(wv.z); Wd[wq + 3][wn] = dup2(wv.w);
        __syncthreads();
#pragma unroll
        for (int kk = 0; kk < 16; kk++) {
            const ulonglong2* ap = (const ulonglong2*)(&As[kk][ty << 3]);
            ulonglong2 av0 = ap[0], av1 = ap[1];
            const ulonglong2* bp = (const ulonglong2*)(&Wd[kk][tx << 2]);
            ulonglong2 bv0 = bp[0], bv1 = bp[1];
            ull a[4] = {av0.x, av0.y, av1.x, av1.y};
            ull b[4] = {bv0.x, bv0.y, bv1.x, bv1.y};
#pragma unroll
            for (int p = 0; p < 4; p++)
#pragma unroll
                for (int j = 0; j < 4; j++) fma2(acc[p][j], a[p], b[j]);
        }
    }
    const int nb = n0 + (tx << 2);
    float bv[4] = {0.f, 0.f, 0.f, 0.f};
    if (bias) { bv[0] = bias[nb]; bv[1] = bias[nb+1]; bv[2] = bias[nb+2]; bv[3] = bias[nb+3]; }
#pragma unroll
    for (int p = 0; p < 4; p++) {
        const size_t r = (size_t)m0 + (ty << 3) + (p << 1);
        float o0[4], o1[4];
#pragma unroll
        for (int j = 0; j < 4; j++) {
            float lo, hi; unpack2(acc[p][j], lo, hi);
            lo += bv[j]; hi += bv[j];
            o0[j] = act ? gelu(lo) : lo;
            o1[j] = act ? gelu(hi) : hi;
        }
        *(float4*)(C + r * N + nb)       = make_float4(o0[0], o0[1], o0[2], o0[3]);
        *(float4*)(C + (r + 1) * N + nb) = make_float4(o1[0], o1[1], o1[2], o1[3]);
    }
}

// ---------------- router: softmax(mid @ Wr^T + br) -> pw[B,16] ----------------
__global__ void __launch_bounds__(256) k_router(
    const float* __restrict__ mid, const float* __restrict__ Wr,
    const float* __restrict__ br, float* __restrict__ pw)
{
    __shared__ float Wrs[16][256];
    const int tid = threadIdx.x;
    for (int i = tid; i < 16 * 256; i += 256) Wrs[i >> 8][i & 255] = Wr[i];
    __syncthreads();
    const int w = tid >> 5, l = tid & 31;
    const size_t b = (size_t)blockIdx.x * 8 + w;
    float x8[8];
#pragma unroll
    for (int m = 0; m < 8; m++) x8[m] = mid[b * 256 + m * 32 + l];
    float acc[16];
#pragma unroll
    for (int n = 0; n < 16; n++) {
        float a = 0.f;
#pragma unroll
        for (int m = 0; m < 8; m++) a += x8[m] * Wrs[n][m * 32 + l];
        acc[n] = a;
    }
#pragma unroll
    for (int n = 0; n < 16; n++) {
#pragma unroll
        for (int off = 16; off >= 1; off >>= 1)
            acc[n] += __shfl_xor_sync(0xffffffffu, acc[n], off);
        acc[n] += br[n];
    }
    float mx = acc[0];
#pragma unroll
    for (int n = 1; n < 16; n++) mx = fmaxf(mx, acc[n]);
    float s = 0.f;
#pragma unroll
    for (int n = 0; n < 16; n++) { acc[n] = expf(acc[n] - mx); s += acc[n]; }
    const float inv = 1.f / s;
    float v = 0.f;
#pragma unroll
    for (int n = 0; n < 16; n++) if (l == n) v = acc[n] * inv;
    if (l < 16) pw[b * 16 + l] = v;
}

// ---------------- combine: mid_out = gelu(sum_g pw*part + b3*sum_g pw) ----------------
__global__ void __launch_bounds__(256) k_combine(
    const float* __restrict__ part, const float* __restrict__ pw,
    const float* __restrict__ b3, float* __restrict__ mo)
{
    const size_t t = (size_t)blockIdx.x * 256 + threadIdx.x;   // over B*128
    const size_t b = t >> 7;
    const int j = (int)(t & 127);
    const int o = j >> 5;
    const float p0 = pw[b * 16 + 0 + o], p1 = pw[b * 16 + 4 + o];
    const float p2 = pw[b * 16 + 8 + o], p3 = pw[b * 16 + 12 + o];
    const size_t gs = (size_t)BATCH * 128, idx = b * 128 + j;
    float v = p0 * part[idx] + p1 * part[gs + idx] + p2 * part[2 * gs + idx] + p3 * part[3 * gs + idx];
    v += b3[j] * (p0 + p1 + p2 + p3);
    mo[idx] = gelu(v);
}

// ---------------- fused tail: L4(128->64) L5(64->32) L6(32->10) ----------------
#define XS_STR 132
#define W4_STR 132
#define W5_STR 68
#define W6_STR 36
#define H4_STR 68
#define H5_STR 36
#define TAIL_SMEM_FLOATS 18642
__global__ void __launch_bounds__(256) k_tail(
    const float* __restrict__ mo,
    const float* __restrict__ W4, const float* __restrict__ b4,
    const float* __restrict__ W5, const float* __restrict__ b5,
    const float* __restrict__ W6, const float* __restrict__ b6,
    float* __restrict__ out)
{
    extern __shared__ float sm[];
    float* xs  = sm;                       // 32 x 132
    float* W4s = xs  + 32 * XS_STR;        // 64 x 132
    float* W5s = W4s + 64 * W4_STR;        // 32 x 68
    float* W6s = W5s + 32 * W5_STR;        // 10 x 36
    float* h4s = W6s + 10 * W6_STR;        // 32 x 68
    float* h5s = h4s + 32 * H4_STR;        // 32 x 36
    float* bs  = h5s + 32 * H5_STR;        // 106
    const int tid = threadIdx.x;
    for (int i = tid; i < 64 * 128; i += 256) W4s[(i >> 7) * W4_STR + (i & 127)] = W4[i];
    for (int i = tid; i < 32 * 64;  i += 256) W5s[(i >> 6) * W5_STR + (i & 63)]  = W5[i];
    for (int i = tid; i < 10 * 32;  i += 256) W6s[(i >> 5) * W6_STR + (i & 31)]  = W6[i];
    if (tid < 64) bs[tid] = b4[tid];
    else if (tid < 96) bs[tid] = b5[tid - 64];
    else if (tid < 106) bs[tid] = b6[tid - 96];
    const size_t row0 = (size_t)blockIdx.x * 32;
    for (int i = tid; i < 32 * 128; i += 256) xs[(i >> 7) * XS_STR + (i & 127)] = mo[row0 * 128 + i];
    __syncthreads();
    const int r = tid >> 3, s = tid & 7;
#pragma unroll
    for (int n8 = 0; n8 < 8; n8++) {
        const int n = s + 8 * n8;          // strided -> conflict-free float4 smem
        float a = bs[n];
#pragma unroll 8
        for (int k = 0; k < 128; k += 4) {
            float4 xv = *(const float4*)&xs[r * XS_STR + k];
            float4 wv = *(const float4*)&W4s[n * W4_STR + k];
            a += xv.x * wv.x + xv.y * wv.y + xv.z * wv.z + xv.w * wv.w;
        }
        h4s[r * H4_STR + n] = gelu(a);
    }
    __syncthreads();
#pragma unroll
    for (int n4 = 0; n4 < 4; n4++) {
        const int n = s + 8 * n4;
        float a = bs[64 + n];
#pragma unroll
        for (int k = 0; k < 64; k += 4) {
            float4 xv = *(const float4*)&h4s[r * H4_STR + k];
            float4 wv = *(const float4*)&W5s[n * W5_STR + k];
            a += xv.x * wv.x + xv.y * wv.y + xv.z * wv.z + xv.w * wv.w;
        }
        h5s[r * H5_STR + n] = gelu(a);
    }
    __syncthreads();
    if (s < 5) {
#pragma unroll
        for (int q = 0; q < 2; q++) {
            const int n = s + 5 * q;
            float a = bs[96 + n];
#pragma unroll
            for (int k = 0; k < 32; k++) a += h5s[r * H5_STR + k] * W6s[n * W6_STR + k];
            out[(row0 + r) * 10 + n] = a;
        }
    }
}

// ---------------- launch ----------------
extern "C" void kernel_launch(void* const* d_in, const int* in_sizes, int n_in,
                              void* d_out, int out_size)
{
    const float* x  = (const float*)d_in[0];
    const float* W1 = (const float*)d_in[1];  const float* b1 = (const float*)d_in[2];
    const float* W2 = (const float*)d_in[3];  const float* b2 = (const float*)d_in[4];
    const float* W3 = (const float*)d_in[5];  const float* b3 = (const float*)d_in[6];
    const float* W4 = (const float*)d_in[7];  const float* b4 = (const float*)d_in[8];
    const float* W5 = (const float*)d_in[9];  const float* b5 = (const float*)d_in[10];
    const float* W6 = (const float*)d_in[11]; const float* b6 = (const float*)d_in[12];
    const float* Wr = (const float*)d_in[13]; const float* br = (const float*)d_in[14];
    float* out = (float*)d_out;

    float *h1, *mid, *pw, *part, *mo;
    cudaGetSymbolAddress((void**)&h1,  g_h1);
    cudaGetSymbolAddress((void**)&mid, g_mid);
    cudaGetSymbolAddress((void**)&pw,  g_pw);
    cudaGetSymbolAddress((void**)&part, g_part);
    cudaGetSymbolAddress((void**)&mo,  g_mo);

    cudaFuncSetAttribute(k_tail, cudaFuncAttributeMaxDynamicSharedMemorySize,
                         TAIL_SMEM_FLOATS * 4);

    const int MB = BATCH / 128;
    // L1: [B,784] -> [B,512]
    k_dense<<<dim3(512 / 64, MB), 256>>>(x, W1, b1, h1, 784, 512, 784, 784, 1);
    // L2: [B,512] -> [B,256]
    k_dense<<<dim3(256 / 64, MB), 256>>>(h1, W2, b2, mid, 512, 256, 512, 512, 1);
    // router
    k_router<<<BATCH / 8, 256>>>(mid, Wr, br, pw);
    // grouped L3 partials: 4 GEMMs, K=64 slices (strided lda/ldw), no bias/act
    for (int g = 0; g < 4; g++) {
        k_dense<<<dim3(128 / 64, MB), 256>>>(
            mid + g * 64, W3 + g * 64, nullptr,
            part + (size_t)g * BATCH * 128, 64, 128, 256, 256, 0);
    }
    // combine with pathway weights + gelu
    k_combine<<<(BATCH * 128) / 256, 256>>>(part, pw, b3, mo);
    // fused L4/L5/L6
    k_tail<<<BATCH / 32, 256, TAIL_SMEM_FLOATS * 4>>>(mo, W4, b4, W5, b5, W6, b6, out);
}

// round 10
// speedup vs baseline: 2.0542x; 2.0542x over previous
#include <cuda_runtime.h>
#include <cstdint>
#include <cstddef>

typedef unsigned long long ull;
#define BATCH 131072

// ---------------- f32x2 packed FMA helpers (PTX-only FFMA2) ----------------
__device__ __forceinline__ ull dup2(float v) {
    ull r;
    asm("mov.b64 %0, {%1, %1};" : "=l"(r) : "r"(__float_as_uint(v)));
    return r;
}
__device__ __forceinline__ void unpack2(ull v, float& lo, float& hi) {
    unsigned a, b;
    asm("mov.b64 {%0, %1}, %2;" : "=r"(a), "=r"(b) : "l"(v));
    lo = __uint_as_float(a); hi = __uint_as_float(b);
}
__device__ __forceinline__ void fma2(ull& d, ull a, ull b) {
    asm("fma.rn.f32x2 %0, %1, %2, %0;" : "+l"(d) : "l"(a), "l"(b));
}
__device__ __forceinline__ float gelu(float x) {
    return 0.5f * x * (1.0f + erff(x * 0.70710678118654752440f));
}

// ---------------- scratch (device globals; no cudaMalloc) ----------------
__device__ float g_h1[(size_t)BATCH * 512];
__device__ float g_mid[(size_t)BATCH * 256];
__device__ float g_pw[(size_t)BATCH * 16];
__device__ float g_part[(size_t)4 * BATCH * 128];
__device__ float g_mo[(size_t)BATCH * 128];

// ---------------------------------------------------------------------------
// GEMM: C[M,N] = act(A[M,K(lda)] @ W[N,K(ldw)]^T + bias)
// BM=128 BN=128 BK=16, 256 threads. Warp tile 32(M)x64(N);
// lane tile 8(M as 4 f32x2 pairs) x 8(N). B unduplicated in smem,
// dup'd to f32x2 in registers. Requires N%128==0, K%16==0, M%128==0.
// ---------------------------------------------------------------------------
__global__ void __launch_bounds__(256, 2) k_dense(
    const float* __restrict__ A, const float* __restrict__ W,
    const float* __restrict__ bias, float* __restrict__ C,
    int K, int N, int lda, int ldw, int act)
{
    __shared__ float As[16][128];
    __shared__ float Bs[16][128];

    const int tid = threadIdx.x;
    const int m0 = blockIdx.y << 7, n0 = blockIdx.x << 7;

    // global loaders: 2 threads per row, each fetches 8 consecutive k
    const int ldr = tid >> 1;
    const int ldk = (tid & 1) << 3;
    const float* Ap = A + (size_t)(m0 + ldr) * lda + ldk;
    const float* Wp = W + (size_t)(n0 + ldr) * ldw + ldk;

    // compute mapping
    const int w = tid >> 5, l = tid & 31;
    const int fm = ((w & 3) << 5) + ((l & 3) << 3);   // row base in tile (0..120)
    const int fn = ((w >> 2) << 6) + ((l >> 2) << 3); // col base in tile (0..120)

    ull acc[4][8];
#pragma unroll
    for (int p = 0; p < 4; p++)
#pragma unroll
        for (int j = 0; j < 8; j++) acc[p][j] = 0ULL;

    float4 a0 = *(const float4*)(Ap);
    float4 a1 = *(const float4*)(Ap + 4);
    float4 w0 = *(const float4*)(Wp);
    float4 w1 = *(const float4*)(Wp + 4);

    int k0 = 0;
    for (;;) {
        // stage current tile into smem
        As[ldk + 0][ldr] = a0.x; As[ldk + 1][ldr] = a0.y;
        As[ldk + 2][ldr] = a0.z; As[ldk + 3][ldr] = a0.w;
        As[ldk + 4][ldr] = a1.x; As[ldk + 5][ldr] = a1.y;
        As[ldk + 6][ldr] = a1.z; As[ldk + 7][ldr] = a1.w;
        Bs[ldk + 0][ldr] = w0.x; Bs[ldk + 1][ldr] = w0.y;
        Bs[ldk + 2][ldr] = w0.z; Bs[ldk + 3][ldr] = w0.w;
        Bs[ldk + 4][ldr] = w1.x; Bs[ldk + 5][ldr] = w1.y;
        Bs[ldk + 6][ldr] = w1.z; Bs[ldk + 7][ldr] = w1.w;
        __syncthreads();

        k0 += 16;
        const bool more = (k0 < K);
        if (more) {  // prefetch next tile into registers during compute
            a0 = *(const float4*)(Ap + k0);
            a1 = *(const float4*)(Ap + k0 + 4);
            w0 = *(const float4*)(Wp + k0);
            w1 = *(const float4*)(Wp + k0 + 4);
        }

#pragma unroll
        for (int kk = 0; kk < 16; kk++) {
            // A: 4 f32x2 pairs (8 rows) -- 2x LDS.128, 4 unique addrs/warp
            const ulonglong2* ap = (const ulonglong2*)&As[kk][fm];
            ulonglong2 av0 = ap[0], av1 = ap[1];
            // B: 8 floats -- 2x LDS.128, 8 unique addrs/warp; dup in regs
            const float4* bp = (const float4*)&Bs[kk][fn];
            float4 b0 = bp[0], b1 = bp[1];
            ull a[4] = {av0.x, av0.y, av1.x, av1.y};
            ull b[8] = {dup2(b0.x), dup2(b0.y), dup2(b0.z), dup2(b0.w),
                        dup2(b1.x), dup2(b1.y), dup2(b1.z), dup2(b1.w)};
#pragma unroll
            for (int p = 0; p < 4; p++)
#pragma unroll
                for (int j = 0; j < 8; j++) fma2(acc[p][j], a[p], b[j]);
        }

        if (!more) break;
        __syncthreads();
    }

    // epilogue
    const int nb = n0 + fn;
    float bv[8] = {0.f, 0.f, 0.f, 0.f, 0.f, 0.f, 0.f, 0.f};
    if (bias) {
        float4 q0 = *(const float4*)(bias + nb);
        float4 q1 = *(const float4*)(bias + nb + 4);
        bv[0] = q0.x; bv[1] = q0.y; bv[2] = q0.z; bv[3] = q0.w;
        bv[4] = q1.x; bv[5] = q1.y; bv[6] = q1.z; bv[7] = q1.w;
    }
#pragma unroll
    for (int p = 0; p < 4; p++) {
        const size_t r = (size_t)m0 + fm + (p << 1);
        float o0[8], o1[8];
#pragma unroll
        for (int j = 0; j < 8; j++) {
            float lo, hi; unpack2(acc[p][j], lo, hi);
            lo += bv[j]; hi += bv[j];
            o0[j] = act ? gelu(lo) : lo;
            o1[j] = act ? gelu(hi) : hi;
        }
        *(float4*)(C + r * N + nb)           = make_float4(o0[0], o0[1], o0[2], o0[3]);
        *(float4*)(C + r * N + nb + 4)       = make_float4(o0[4], o0[5], o0[6], o0[7]);
        *(float4*)(C + (r + 1) * N + nb)     = make_float4(o1[0], o1[1], o1[2], o1[3]);
        *(float4*)(C + (r + 1) * N + nb + 4) = make_float4(o1[4], o1[5], o1[6], o1[7]);
    }
}

// ---------------- router: softmax(mid @ Wr^T + br) -> pw[B,16] ----------------
__global__ void __launch_bounds__(256) k_router(
    const float* __restrict__ mid, const float* __restrict__ Wr,
    const float* __restrict__ br, float* __restrict__ pw)
{
    __shared__ float Wrs[16][256];
    const int tid = threadIdx.x;
    for (int i = tid; i < 16 * 256; i += 256) Wrs[i >> 8][i & 255] = Wr[i];
    __syncthreads();
    const int w = tid >> 5, l = tid & 31;
    const size_t b = (size_t)blockIdx.x * 8 + w;
    float x8[8];
#pragma unroll
    for (int m = 0; m < 8; m++) x8[m] = mid[b * 256 + m * 32 + l];
    float acc[16];
#pragma unroll
    for (int n = 0; n < 16; n++) {
        float a = 0.f;
#pragma unroll
        for (int m = 0; m < 8; m++) a += x8[m] * Wrs[n][m * 32 + l];
        acc[n] = a;
    }
#pragma unroll
    for (int n = 0; n < 16; n++) {
#pragma unroll
        for (int off = 16; off >= 1; off >>= 1)
            acc[n] += __shfl_xor_sync(0xffffffffu, acc[n], off);
        acc[n] += br[n];
    }
    float mx = acc[0];
#pragma unroll
    for (int n = 1; n < 16; n++) mx = fmaxf(mx, acc[n]);
    float s = 0.f;
#pragma unroll
    for (int n = 0; n < 16; n++) { acc[n] = expf(acc[n] - mx); s += acc[n]; }
    const float inv = 1.f / s;
    float v = 0.f;
#pragma unroll
    for (int n = 0; n < 16; n++) if (l == n) v = acc[n] * inv;
    if (l < 16) pw[b * 16 + l] = v;
}

// ------------- combine: mid_out = gelu(sum_g pw*part + b3*sum_g pw) -------------
__global__ void __launch_bounds__(256) k_combine(
    const float* __restrict__ part, const float* __restrict__ pw,
    const float* __restrict__ b3, float* __restrict__ mo)
{
    const size_t t = (size_t)blockIdx.x * 256 + threadIdx.x;   // over B*128
    const size_t b = t >> 7;
    const int j = (int)(t & 127);
    const int o = j >> 5;
    const float p0 = pw[b * 16 + 0 + o], p1 = pw[b * 16 + 4 + o];
    const float p2 = pw[b * 16 + 8 + o], p3 = pw[b * 16 + 12 + o];
    const size_t gs = (size_t)BATCH * 128, idx = b * 128 + j;
    float v = p0 * part[idx] + p1 * part[gs + idx] + p2 * part[2 * gs + idx] + p3 * part[3 * gs + idx];
    v += b3[j] * (p0 + p1 + p2 + p3);
    mo[idx] = gelu(v);
}

// ---------------- fused tail: L4(128->64) L5(64->32) L6(32->10) ----------------
#define XS_STR 132
#define W4_STR 132
#define W5_STR 68
#define W6_STR 36
#define H4_STR 68
#define H5_STR 36
#define TAIL_SMEM_FLOATS 18642
__global__ void __launch_bounds__(256) k_tail(
    const float* __restrict__ mo,
    const float* __restrict__ W4, const float* __restrict__ b4,
    const float* __restrict__ W5, const float* __restrict__ b5,
    const float* __restrict__ W6, const float* __restrict__ b6,
    float* __restrict__ out)
{
    extern __shared__ float sm[];
    float* xs  = sm;                       // 32 x 132
    float* W4s = xs  + 32 * XS_STR;        // 64 x 132
    float* W5s = W4s + 64 * W4_STR;        // 32 x 68
    float* W6s = W5s + 32 * W5_STR;        // 10 x 36
    float* h4s = W6s + 10 * W6_STR;        // 32 x 68
    float* h5s = h4s + 32 * H4_STR;        // 32 x 36
    float* bs  = h5s + 32 * H5_STR;        // 106
    const int tid = threadIdx.x;
    for (int i = tid; i < 64 * 128; i += 256) W4s[(i >> 7) * W4_STR + (i & 127)] = W4[i];
    for (int i = tid; i < 32 * 64;  i += 256) W5s[(i >> 6) * W5_STR + (i & 63)]  = W5[i];
    for (int i = tid; i < 10 * 32;  i += 256) W6s[(i >> 5) * W6_STR + (i & 31)]  = W6[i];
    if (tid < 64) bs[tid] = b4[tid];
    else if (tid < 96) bs[tid] = b5[tid - 64];
    else if (tid < 106) bs[tid] = b6[tid - 96];
    const size_t row0 = (size_t)blockIdx.x * 32;
    for (int i = tid; i < 32 * 128; i += 256) xs[(i >> 7) * XS_STR + (i & 127)] = mo[row0 * 128 + i];
    __syncthreads();
    const int r = tid >> 3, s = tid & 7;
#pragma unroll
    for (int n8 = 0; n8 < 8; n8++) {
        const int n = s + 8 * n8;
        float a = bs[n];
#pragma unroll 8
        for (int k = 0; k < 128; k += 4) {
            float4 xv = *(const float4*)&xs[r * XS_STR + k];
            float4 wv = *(const float4*)&W4s[n * W4_STR + k];
            a += xv.x * wv.x + xv.y * wv.y + xv.z * wv.z + xv.w * wv.w;
        }
        h4s[r * H4_STR + n] = gelu(a);
    }
    __syncthreads();
#pragma unroll
    for (int n4 = 0; n4 < 4; n4++) {
        const int n = s + 8 * n4;
        float a = bs[64 + n];
#pragma unroll
        for (int k = 0; k < 64; k += 4) {
            float4 xv = *(const float4*)&h4s[r * H4_STR + k];
            float4 wv = *(const float4*)&W5s[n * W5_STR + k];
            a += xv.x * wv.x + xv.y * wv.y + xv.z * wv.z + xv.w * wv.w;
        }
        h5s[r * H5_STR + n] = gelu(a);
    }
    __syncthreads();
    if (s < 5) {
#pragma unroll
        for (int q = 0; q < 2; q++) {
            const int n = s + 5 * q;
            float a = bs[96 + n];
#pragma unroll
            for (int k = 0; k < 32; k++) a += h5s[r * H5_STR + k] * W6s[n * W6_STR + k];
            out[(row0 + r) * 10 + n] = a;
        }
    }
}

// ---------------- launch ----------------
extern "C" void kernel_launch(void* const* d_in, const int* in_sizes, int n_in,
                              void* d_out, int out_size)
{
    const float* x  = (const float*)d_in[0];
    const float* W1 = (const float*)d_in[1];  const float* b1 = (const float*)d_in[2];
    const float* W2 = (const float*)d_in[3];  const float* b2 = (const float*)d_in[4];
    const float* W3 = (const float*)d_in[5];  const float* b3 = (const float*)d_in[6];
    const float* W4 = (const float*)d_in[7];  const float* b4 = (const float*)d_in[8];
    const float* W5 = (const float*)d_in[9];  const float* b5 = (const float*)d_in[10];
    const float* W6 = (const float*)d_in[11]; const float* b6 = (const float*)d_in[12];
    const float* Wr = (const float*)d_in[13]; const float* br = (const float*)d_in[14];
    float* out = (float*)d_out;

    float *h1, *mid, *pw, *part, *mo;
    cudaGetSymbolAddress((void**)&h1,  g_h1);
    cudaGetSymbolAddress((void**)&mid, g_mid);
    cudaGetSymbolAddress((void**)&pw,  g_pw);
    cudaGetSymbolAddress((void**)&part, g_part);
    cudaGetSymbolAddress((void**)&mo,  g_mo);

    cudaFuncSetAttribute(k_tail, cudaFuncAttributeMaxDynamicSharedMemorySize,
                         TAIL_SMEM_FLOATS * 4);

    const int MB = BATCH / 128;
    // L1: [B,784] -> [B,512]
    k_dense<<<dim3(512 / 128, MB), 256>>>(x, W1, b1, h1, 784, 512, 784, 784, 1);
    // L2: [B,512] -> [B,256]
    k_dense<<<dim3(256 / 128, MB), 256>>>(h1, W2, b2, mid, 512, 256, 512, 512, 1);
    // router
    k_router<<<BATCH / 8, 256>>>(mid, Wr, br, pw);
    // grouped L3 partials: 4 GEMMs on K=64 slices (strided lda/ldw)
    for (int g = 0; g < 4; g++) {
        k_dense<<<dim3(128 / 128, MB), 256>>>(
            mid + g * 64, W3 + g * 64, nullptr,
            part + (size_t)g * BATCH * 128, 64, 128, 256, 256, 0);
    }
    // combine with pathway weights + gelu
    k_combine<<<(size_t)(BATCH) * 128 / 256, 256>>>(part, pw, b3, mo);
    // fused L4/L5/L6
    k_tail<<<BATCH / 32, 256, TAIL_SMEM_FLOATS * 4>>>(mo, W4, b4, W5, b5, W6, b6, out);
}

// round 12
// speedup vs baseline: 2.7389x; 1.3333x over previous
#include <cuda_runtime.h>
#include <cuda_bf16.h>
#include <cstdint>
#include <cstddef>

typedef unsigned long long ull;
#define BATCH 131072

// ======================= small helpers =======================
__device__ __forceinline__ ull dup2(float v) {
    ull r; asm("mov.b64 %0, {%1, %1};" : "=l"(r) : "r"(__float_as_uint(v))); return r;
}
__device__ __forceinline__ ull pack2(float lo, float hi) {
    ull r; asm("mov.b64 %0, {%1, %2};" : "=l"(r)
               : "r"(__float_as_uint(lo)), "r"(__float_as_uint(hi))); return r;
}
__device__ __forceinline__ void unpack2(ull v, float& lo, float& hi) {
    unsigned a, b; asm("mov.b64 {%0, %1}, %2;" : "=r"(a), "=r"(b) : "l"(v));
    lo = __uint_as_float(a); hi = __uint_as_float(b);
}
__device__ __forceinline__ void fma2(ull& d, ull a, ull b) {
    asm("fma.rn.f32x2 %0, %1, %2, %0;" : "+l"(d) : "l"(a), "l"(b));
}
__device__ __forceinline__ float gelu(float x) {
    return 0.5f * x * (1.0f + erff(x * 0.70710678118654752440f));
}
__device__ __forceinline__ uint32_t smem_u32(const void* p) {
    uint32_t a;
    asm("{ .reg .u64 t; cvta.to.shared.u64 t, %1; cvt.u32.u64 %0, t; }" : "=r"(a) : "l"(p));
    return a;
}

// split a float pair into bf16-hi packed word and bf16-lo (residual) packed word
__device__ __forceinline__ void cvt_split2(float x, float y, uint32_t& hw, uint32_t& lw) {
    asm("cvt.rn.bf16x2.f32 %0, %1, %2;" : "=r"(hw) : "f"(y), "f"(x));
    float hx = __uint_as_float(hw << 16);
    float hy = __uint_as_float(hw & 0xFFFF0000u);
    float rx = x - hx, ry = y - hy;
    asm("cvt.rn.bf16x2.f32 %0, %1, %2;" : "=r"(lw) : "f"(ry), "f"(rx));
}

#define LDSM_X4(r, adr) \
    asm volatile("ldmatrix.sync.aligned.m8n8.x4.shared.b16 {%0,%1,%2,%3}, [%4];" \
        : "=r"((r)[0]), "=r"((r)[1]), "=r"((r)[2]), "=r"((r)[3]) : "r"(adr))
#define LDSM_X4T(r, adr) \
    asm volatile("ldmatrix.sync.aligned.m8n8.x4.trans.shared.b16 {%0,%1,%2,%3}, [%4];" \
        : "=r"((r)[0]), "=r"((r)[1]), "=r"((r)[2]), "=r"((r)[3]) : "r"(adr))
#define MMA_BF16(d, a, b0, b1) \
    asm volatile("mma.sync.aligned.m16n8k16.row.col.f32.bf16.bf16.f32 " \
        "{%0,%1,%2,%3}, {%4,%5,%6,%7}, {%8,%9}, {%0,%1,%2,%3};" \
        : "+f"((d)[0]), "+f"((d)[1]), "+f"((d)[2]), "+f"((d)[3]) \
        : "r"((a)[0]), "r"((a)[1]), "r"((a)[2]), "r"((a)[3]), "r"(b0), "r"(b1))

// ======================= scratch =======================
__device__ float g_h1[(size_t)BATCH * 512];
__device__ float g_mid[(size_t)BATCH * 256];
__device__ float g_pw[(size_t)BATCH * 16];
__device__ float g_mo[(size_t)BATCH * 128];

// ======================= k_hmma: C = gelu(A[M,K] @ W[N,K]^T + b) =======================
// bf16-split (AH*BH + AL*BH + AH*BL) via mma.sync m16n8k16, fp32 accum.
// CTA 128x128, BK=32, 256 thr (8 warps, warp tile 32x64).
#define STR 40   // bf16 elements per smem row (32 + 8 pad) -> conflict-free ldmatrix

__global__ void __launch_bounds__(256, 1) k_hmma(
    const float* __restrict__ A, const float* __restrict__ W,
    const float* __restrict__ bias, float* __restrict__ C, int K, int N)
{
    __shared__ ushort AsH[128 * STR], AsL[128 * STR];
    __shared__ ushort BsH[128 * STR], BsL[128 * STR];

    const int tid = threadIdx.x;
    const int lane = tid & 31, wid = tid >> 5;
    const int wm = wid & 3, wn = wid >> 2;
    const int m0 = blockIdx.y << 7, n0 = blockIdx.x << 7;

    // loader mapping: 2 threads per row, 16 k each
    const int lrow = tid >> 1, lkb = (tid & 1) << 4;
    const float* Ap = A + (size_t)(m0 + lrow) * K;
    const float* Wp = W + (size_t)(n0 + lrow) * K;

    float acc[2][8][4];
#pragma unroll
    for (int mt = 0; mt < 2; mt++)
#pragma unroll
        for (int nt = 0; nt < 8; nt++)
#pragma unroll
            for (int d = 0; d < 4; d++) acc[mt][nt][d] = 0.f;

    const int nst = (K + 31) >> 5;
    float4 ra[4], rb[4];
    const float4 z4 = make_float4(0.f, 0.f, 0.f, 0.f);
#pragma unroll
    for (int q = 0; q < 4; q++) {
        int k = lkb + q * 4;
        ra[q] = (k < K) ? *(const float4*)(Ap + k) : z4;
        rb[q] = (k < K) ? *(const float4*)(Wp + k) : z4;
    }

    // precomputed ldmatrix smem addresses (byte addresses of row starts)
    const int a_r = (lane & 15);
    const int a_k = (lane >> 4) << 3;
    const int b_n = ((lane >> 4) << 3) + (lane & 7);
    const int b_k = ((lane >> 3) & 1) << 3;

    for (int s = 0; s < nst; s++) {
        __syncthreads();
#pragma unroll
        for (int q = 0; q < 4; q++) {
            uint32_t h0, l0, h1, l1;
            const int off = lrow * STR + lkb + q * 4;
            cvt_split2(ra[q].x, ra[q].y, h0, l0);
            cvt_split2(ra[q].z, ra[q].w, h1, l1);
            *(uint2*)&AsH[off] = make_uint2(h0, h1);
            *(uint2*)&AsL[off] = make_uint2(l0, l1);
            cvt_split2(rb[q].x, rb[q].y, h0, l0);
            cvt_split2(rb[q].z, rb[q].w, h1, l1);
            *(uint2*)&BsH[off] = make_uint2(h0, h1);
            *(uint2*)&BsL[off] = make_uint2(l0, l1);
        }
        __syncthreads();
        if (s + 1 < nst) {
            const int k0n = (s + 1) << 5;
#pragma unroll
            for (int q = 0; q < 4; q++) {
                int k = k0n + lkb + q * 4;
                ra[q] = (k < K) ? *(const float4*)(Ap + k) : z4;
                rb[q] = (k < K) ? *(const float4*)(Wp + k) : z4;
            }
        }
#pragma unroll
        for (int ks = 0; ks < 32; ks += 16) {
            uint32_t ah[2][4], al[2][4];
#pragma unroll
            for (int mt = 0; mt < 2; mt++) {
                const int row = wm * 32 + mt * 16 + a_r;
                const int kc = ks + a_k;
                LDSM_X4(ah[mt], smem_u32(&AsH[row * STR + kc]));
                LDSM_X4(al[mt], smem_u32(&AsL[row * STR + kc]));
            }
            uint32_t bh[4][4], bl[4][4];
#pragma unroll
            for (int np = 0; np < 4; np++) {
                const int n = wn * 64 + np * 16 + b_n;
                const int kc = ks + b_k;
                LDSM_X4T(bh[np], smem_u32(&BsH[n * STR + kc]));
                LDSM_X4T(bl[np], smem_u32(&BsL[n * STR + kc]));
            }
#pragma unroll
            for (int mt = 0; mt < 2; mt++)
#pragma unroll
                for (int nt = 0; nt < 8; nt++) {
                    const int np = nt >> 1, q = (nt & 1) << 1;
                    MMA_BF16(acc[mt][nt], ah[mt], bh[np][q], bh[np][q + 1]);
                    MMA_BF16(acc[mt][nt], al[mt], bh[np][q], bh[np][q + 1]);
                    MMA_BF16(acc[mt][nt], ah[mt], bl[np][q], bl[np][q + 1]);
                }
        }
    }

    // epilogue: D frag (row = gid(+8), col = tig*2(+1))
    const int gid = lane >> 2, tig = lane & 3;
#pragma unroll
    for (int nt = 0; nt < 8; nt++) {
        const int col = n0 + wn * 64 + nt * 8 + tig * 2;
        const float b0 = bias[col], b1 = bias[col + 1];
#pragma unroll
        for (int mt = 0; mt < 2; mt++) {
            const size_t r0 = (size_t)m0 + wm * 32 + mt * 16 + gid;
            float2 v;
            v.x = gelu(acc[mt][nt][0] + b0);
            v.y = gelu(acc[mt][nt][1] + b1);
            *(float2*)(C + r0 * N + col) = v;
            v.x = gelu(acc[mt][nt][2] + b0);
            v.y = gelu(acc[mt][nt][3] + b1);
            *(float2*)(C + (r0 + 8) * N + col) = v;
        }
    }
}

// ======================= k_router =======================
__global__ void __launch_bounds__(256) k_router(
    const float* __restrict__ mid, const float* __restrict__ Wr,
    const float* __restrict__ br, float* __restrict__ pw)
{
    __shared__ float Wrs[16][256];
    const int tid = threadIdx.x;
    for (int i = tid; i < 16 * 256; i += 256) Wrs[i >> 8][i & 255] = Wr[i];
    __syncthreads();
    const int w = tid >> 5, l = tid & 31;
    const size_t b = (size_t)blockIdx.x * 8 + w;
    float x8[8];
#pragma unroll
    for (int m = 0; m < 8; m++) x8[m] = mid[b * 256 + m * 32 + l];
    float acc[16];
#pragma unroll
    for (int n = 0; n < 16; n++) {
        float a = 0.f;
#pragma unroll
        for (int m = 0; m < 8; m++) a += x8[m] * Wrs[n][m * 32 + l];
        acc[n] = a;
    }
#pragma unroll
    for (int n = 0; n < 16; n++) {
#pragma unroll
        for (int off = 16; off >= 1; off >>= 1)
            acc[n] += __shfl_xor_sync(0xffffffffu, acc[n], off);
        acc[n] += br[n];
    }
    float mx = acc[0];
#pragma unroll
    for (int n = 1; n < 16; n++) mx = fmaxf(mx, acc[n]);
    float s = 0.f;
#pragma unroll
    for (int n = 0; n < 16; n++) { acc[n] = expf(acc[n] - mx); s += acc[n]; }
    const float inv = 1.f / s;
    float v = 0.f;
#pragma unroll
    for (int n = 0; n < 16; n++) if (l == n) v = acc[n] * inv;
    if (l < 16) pw[b * 16 + l] = v;
}

// ======================= k_mid: fused grouped L3 + router weighting + gelu =======================
__global__ void __launch_bounds__(256) k_mid(
    const float* __restrict__ mid, const float* __restrict__ W3,
    const float* __restrict__ b3, const float* __restrict__ pw,
    float* __restrict__ mo)
{
    __shared__ float As[16][128];
    __shared__ float Bs[16][64];
    const int tid = threadIdx.x;
    const int m0 = blockIdx.y << 7, n0 = blockIdx.x << 6;
    const int a_ldr = tid >> 1, a_ldk = (tid & 1) << 3;
    const int b_ldr = tid >> 2, b_ldk = (tid & 3) << 2;
    const int w = tid >> 5, l = tid & 31;
    const int fm = ((w & 3) << 5) + ((l & 3) << 3);
    const int fn = ((w >> 2) << 5) + ((l >> 2) << 2);
    const int og = (n0 + fn) >> 5;

    const float* Ap = mid + (size_t)(m0 + a_ldr) * 256 + a_ldk;
    const float* Wp = W3 + (size_t)(n0 + b_ldr) * 256 + b_ldk;

    float pwv[4][8];
#pragma unroll
    for (int g = 0; g < 4; g++)
#pragma unroll
        for (int i = 0; i < 8; i++)
            pwv[g][i] = pw[(size_t)(m0 + fm + i) * 16 + g * 4 + og];

    ull facc[4][4], acc[4][4];
#pragma unroll
    for (int p = 0; p < 4; p++)
#pragma unroll
        for (int j = 0; j < 4; j++) { facc[p][j] = 0ULL; acc[p][j] = 0ULL; }

    float4 a0 = *(const float4*)(Ap);
    float4 a1 = *(const float4*)(Ap + 4);
    float4 w0 = *(const float4*)(Wp);

    for (int t = 0; t < 16; t++) {
        __syncthreads();
        As[a_ldk + 0][a_ldr] = a0.x; As[a_ldk + 1][a_ldr] = a0.y;
        As[a_ldk + 2][a_ldr] = a0.z; As[a_ldk + 3][a_ldr] = a0.w;
        As[a_ldk + 4][a_ldr] = a1.x; As[a_ldk + 5][a_ldr] = a1.y;
        As[a_ldk + 6][a_ldr] = a1.z; As[a_ldk + 7][a_ldr] = a1.w;
        Bs[b_ldk + 0][b_ldr] = w0.x; Bs[b_ldk + 1][b_ldr] = w0.y;
        Bs[b_ldk + 2][b_ldr] = w0.z; Bs[b_ldk + 3][b_ldr] = w0.w;
        __syncthreads();
        if (t < 15) {
            const int t1 = t + 1;
            const int off = (t1 >> 2) * 64 + (t1 & 3) * 16;
            a0 = *(const float4*)(Ap + off);
            a1 = *(const float4*)(Ap + off + 4);
            w0 = *(const float4*)(Wp + off);
        }
#pragma unroll
        for (int kk = 0; kk < 16; kk++) {
            const ulonglong2* ap = (const ulonglong2*)&As[kk][fm];
            ulonglong2 av0 = ap[0], av1 = ap[1];
            float4 bq = *(const float4*)&Bs[kk][fn];
            ull a[4] = {av0.x, av0.y, av1.x, av1.y};
            ull b[4] = {dup2(bq.x), dup2(bq.y), dup2(bq.z), dup2(bq.w)};
#pragma unroll
            for (int p = 0; p < 4; p++)
#pragma unroll
                for (int j = 0; j < 4; j++) fma2(acc[p][j], a[p], b[j]);
        }
        if ((t & 3) == 3) {
            const int g = t >> 2;
#pragma unroll
            for (int p = 0; p < 4; p++) {
                ull pwp = pack2(pwv[g][2 * p], pwv[g][2 * p + 1]);
#pragma unroll
                for (int j = 0; j < 4; j++) { fma2(facc[p][j], pwp, acc[p][j]); acc[p][j] = 0ULL; }
            }
        }
    }

    float psum[8];
#pragma unroll
    for (int i = 0; i < 8; i++)
        psum[i] = pwv[0][i] + pwv[1][i] + pwv[2][i] + pwv[3][i];
    const int nb = n0 + fn;
    float b3v[4] = {b3[nb], b3[nb + 1], b3[nb + 2], b3[nb + 3]};
#pragma unroll
    for (int p = 0; p < 4; p++) {
        const size_t row = (size_t)m0 + fm + (p << 1);
        float o0[4], o1[4];
#pragma unroll
        for (int j = 0; j < 4; j++) {
            float lo, hi; unpack2(facc[p][j], lo, hi);
            o0[j] = gelu(lo + b3v[j] * psum[2 * p]);
            o1[j] = gelu(hi + b3v[j] * psum[2 * p + 1]);
        }
        *(float4*)(mo + row * 128 + nb)       = make_float4(o0[0], o0[1], o0[2], o0[3]);
        *(float4*)(mo + (row + 1) * 128 + nb) = make_float4(o1[0], o1[1], o1[2], o1[3]);
    }
}

// ======================= fused tail: L4 L5 L6 =======================
#define XS_STR 132
#define W4_STR 132
#define W5_STR 68
#define W6_STR 36
#define H4_STR 68
#define H5_STR 36
#define TAIL_SMEM_FLOATS 18642
__global__ void __launch_bounds__(256) k_tail(
    const float* __restrict__ mo,
    const float* __restrict__ W4, const float* __restrict__ b4,
    const float* __restrict__ W5, const float* __restrict__ b5,
    const float* __restrict__ W6, const float* __restrict__ b6,
    float* __restrict__ out)
{
    extern __shared__ float smf[];
    float* xs  = smf;
    float* W4s = xs  + 32 * XS_STR;
    float* W5s = W4s + 64 * W4_STR;
    float* W6s = W5s + 32 * W5_STR;
    float* h4s = W6s + 10 * W6_STR;
    float* h5s = h4s + 32 * H4_STR;
    float* bs  = h5s + 32 * H5_STR;
    const int tid = threadIdx.x;
    for (int i = tid; i < 64 * 128; i += 256) W4s[(i >> 7) * W4_STR + (i & 127)] = W4[i];
    for (int i = tid; i < 32 * 64;  i += 256) W5s[(i >> 6) * W5_STR + (i & 63)]  = W5[i];
    for (int i = tid; i < 10 * 32;  i += 256) W6s[(i >> 5) * W6_STR + (i & 31)]  = W6[i];
    if (tid < 64) bs[tid] = b4[tid];
    else if (tid < 96) bs[tid] = b5[tid - 64];
    else if (tid < 106) bs[tid] = b6[tid - 96];
    const size_t row0 = (size_t)blockIdx.x * 32;
    for (int i = tid; i < 32 * 128; i += 256) xs[(i >> 7) * XS_STR + (i & 127)] = mo[row0 * 128 + i];
    __syncthreads();
    const int r = tid >> 3, s = tid & 7;
#pragma unroll
    for (int n8 = 0; n8 < 8; n8++) {
        const int n = s + 8 * n8;
        float a = bs[n];
#pragma unroll 8
        for (int k = 0; k < 128; k += 4) {
            float4 xv = *(const float4*)&xs[r * XS_STR + k];
            float4 wv = *(const float4*)&W4s[n * W4_STR + k];
            a += xv.x * wv.x + xv.y * wv.y + xv.z * wv.z + xv.w * wv.w;
        }
        h4s[r * H4_STR + n] = gelu(a);
    }
    __syncthreads();
#pragma unroll
    for (int n4 = 0; n4 < 4; n4++) {
        const int n = s + 8 * n4;
        float a = bs[64 + n];
#pragma unroll
        for (int k = 0; k < 64; k += 4) {
            float4 xv = *(const float4*)&h4s[r * H4_STR + k];
            float4 wv = *(const float4*)&W5s[n * W5_STR + k];
            a += xv.x * wv.x + xv.y * wv.y + xv.z * wv.z + xv.w * wv.w;
        }
        h5s[r * H5_STR + n] = gelu(a);
    }
    __syncthreads();
    if (s < 5) {
#pragma unroll
        for (int q = 0; q < 2; q++) {
            const int n = s + 5 * q;
            float a = bs[96 + n];
#pragma unroll
            for (int k = 0; k < 32; k++) a += h5s[r * H5_STR + k] * W6s[n * W6_STR + k];
            out[(row0 + r) * 10 + n] = a;
        }
    }
}

// ======================= launch =======================
extern "C" void kernel_launch(void* const* d_in, const int* in_sizes, int n_in,
                              void* d_out, int out_size)
{
    const float* x  = (const float*)d_in[0];
    const float* W1 = (const float*)d_in[1];  const float* b1 = (const float*)d_in[2];
    const float* W2 = (const float*)d_in[3];  const float* b2 = (const float*)d_in[4];
    const float* W3 = (const float*)d_in[5];  const float* b3 = (const float*)d_in[6];
    const float* W4 = (const float*)d_in[7];  const float* b4 = (const float*)d_in[8];
    const float* W5 = (const float*)d_in[9];  const float* b5 = (const float*)d_in[10];
    const float* W6 = (const float*)d_in[11]; const float* b6 = (const float*)d_in[12];
    const float* Wr = (const float*)d_in[13]; const float* br = (const float*)d_in[14];
    float* out = (float*)d_out;

    float *h1, *mid, *pw, *mo;
    cudaGetSymbolAddress((void**)&h1,  g_h1);
    cudaGetSymbolAddress((void**)&mid, g_mid);
    cudaGetSymbolAddress((void**)&pw,  g_pw);
    cudaGetSymbolAddress((void**)&mo,  g_mo);

    cudaFuncSetAttribute(k_tail, cudaFuncAttributeMaxDynamicSharedMemorySize,
                         TAIL_SMEM_FLOATS * 4);

    const int MB = BATCH / 128;
    // L1: [B,784] -> [B,512]  (bf16-split HMMA)
    k_hmma<<<dim3(512 / 128, MB), 256>>>(x, W1, b1, h1, 784, 512);
    // L2: [B,512] -> [B,256]
    k_hmma<<<dim3(256 / 128, MB), 256>>>(h1, W2, b2, mid, 512, 256);
    // router
    k_router<<<BATCH / 8, 256>>>(mid, Wr, br, pw);
    // fused grouped middle layer
    k_mid<<<dim3(128 / 64, MB), 256>>>(mid, W3, b3, pw, mo);
    // fused L4/L5/L6
    k_tail<<<BATCH / 32, 256, TAIL_SMEM_FLOATS * 4>>>(mo, W4, b4, W5, b5, W6, b6, out);
}